// round 14
// baseline (speedup 1.0000x reference)
#include <cuda_runtime.h>
#include <cuda_fp16.h>
#include <cstdint>

#define NN 8192
#define IN_F 128
#define OUT_F 64
#define TI 128
#define TJ 64
#define JSPLIT 4
#define LALPHA 0.2f
#define NTILES ((NN / JSPLIT) / TJ)   // 32
#define LOG2E 1.4426950408889634f

// -------- scratch (allocation-free) --------
// B in mma-fragment order: [tile 128][kk 4][nb 8][lane 32] x uint2
__device__ uint2 g_Bpk[128 * 4 * 8 * 32];
__device__ float g_f1[NN];                   // pre-scaled by log2(e)
__device__ float g_f2[NN];                   // pre-scaled by log2(e)
__device__ float g_acc[JSPLIT][NN * OUT_F];
__device__ float g_s[JSPLIT][NN];
__device__ int   g_m2i = 0x80000000;         // encoded max(f2_scaled)

__device__ __forceinline__ int enc_f(float x) {
    int k = __float_as_int(x);
    return (k < 0) ? (k ^ 0x7FFFFFFF) : k;
}
__device__ __forceinline__ float dec_f(int k) {
    return __int_as_float((k < 0) ? (k ^ 0x7FFFFFFF) : k);
}
__device__ __forceinline__ uint32_t h2_u32(__half2 h) {
    uint32_t u;
    *(__half2*)&u = h;
    return u;
}
__device__ __forceinline__ float ex2(float x) {
    float y;
    asm("ex2.approx.ftz.f32 %0, %1;" : "=f"(y) : "f"(x));
    return y;
}
__device__ __forceinline__ uint32_t smem_u32(const void* p) {
    uint32_t a;
    asm("{ .reg .u64 t; cvta.to.shared.u64 t, %1; cvt.u32.u64 %0, t; }"
        : "=r"(a) : "l"(p));
    return a;
}
__device__ __forceinline__ void ldsm_x4(uint32_t& r0, uint32_t& r1,
                                        uint32_t& r2, uint32_t& r3,
                                        uint32_t addr) {
    asm volatile("ldmatrix.sync.aligned.m8n8.x4.shared.b16 {%0,%1,%2,%3}, [%4];"
                 : "=r"(r0), "=r"(r1), "=r"(r2), "=r"(r3) : "r"(addr));
}

// m16n8k16 fp16 mma, fp32 accum
__device__ __forceinline__ void mma_f16(float* c, uint32_t a0, uint32_t a1,
                                        uint32_t a2, uint32_t a3,
                                        uint32_t b0, uint32_t b1) {
    asm volatile(
        "mma.sync.aligned.m16n8k16.row.col.f32.f16.f16.f32 "
        "{%0,%1,%2,%3}, {%4,%5,%6,%7}, {%8,%9}, {%0,%1,%2,%3};"
        : "+f"(c[0]), "+f"(c[1]), "+f"(c[2]), "+f"(c[3])
        : "r"(a0), "r"(a1), "r"(a2), "r"(a3), "r"(b0), "r"(b1));
}

// ---------------------------------------------------------------------------
// Kernel 1 (R12, proven 12.4us): Wh = h @ W ; packed B fragments ; f1, f2.
// 32 rows/block x 512 threads -> 256 blocks = one wave at 2 CTAs/SM.
// ---------------------------------------------------------------------------
#define P_SMEM (14496 * 4)   // Ws 8192 | hs 4096 | whs 2080 | a1s 64 | a2s 64

__global__ void __launch_bounds__(512, 2)
k_prep(const float* __restrict__ h,
       const float* __restrict__ W,
       const float* __restrict__ a) {
    extern __shared__ __align__(16) float psm[];
    float* Ws = psm;                                   // [128*64]
    float (*hs)[IN_F] = (float (*)[IN_F])(psm + 8192); // [32][128]
    float (*whs)[65]  = (float (*)[65])(psm + 12288);  // [32][65]
    float* a1s = psm + 14368;
    float* a2s = psm + 14432;

    int t = threadIdx.x;
    int rowbase = blockIdx.x * 32;

    #pragma unroll
    for (int q = 0; q < 4; q++)
        ((float4*)Ws)[t + q * 512] = ((const float4*)W)[t + q * 512];
    #pragma unroll
    for (int q = 0; q < 2; q++)
        ((float4*)hs)[t + q * 512] =
            ((const float4*)(h + (size_t)rowbase * IN_F))[t + q * 512];
    if (t < OUT_F) { a1s[t] = a[t]; a2s[t] = a[OUT_F + t]; }
    __syncthreads();

    int f  = t & 63;
    int rg = t >> 6;          // 0..7, 4 rows each
    float acc[4] = {0.f, 0.f, 0.f, 0.f};
    #pragma unroll 4
    for (int k = 0; k < IN_F; k++) {
        float w = Ws[k * OUT_F + f];
        #pragma unroll
        for (int rr = 0; rr < 4; rr++)
            acc[rr] += hs[rg * 4 + rr][k] * w;
    }
    #pragma unroll
    for (int rr = 0; rr < 4; rr++) whs[rg * 4 + rr][f] = acc[rr];
    __syncthreads();

    // packed B fragment store: two 16-row groups per block.
    {
        int grp = t >> 8;            // 0/1
        int tt  = t & 255;
        int nb  = tt >> 5, l = tt & 31;
        int n   = nb * 8 + (l >> 2);
        int jl  = grp * 16 + (l & 3) * 2;
        __half2 w0 = __floats2half2_rn(whs[jl][n],     whs[jl + 1][n]);
        __half2 w1 = __floats2half2_rn(whs[jl + 8][n], whs[jl + 9][n]);
        int rb = rowbase + grp * 16;
        int T  = rb >> 6;
        int kk = (rb >> 4) & 3;
        size_t idx = ((size_t)(T * 4 + kk) * 8 + nb) * 32 + l;
        g_Bpk[idx] = make_uint2(h2_u32(w0), h2_u32(w1));
    }

    if (t < 32) {
        float s1 = 0.f, s2 = 0.f;
        #pragma unroll 8
        for (int ff = 0; ff < OUT_F; ff++) {
            float v = whs[t][ff];
            s1 += v * a1s[ff];
            s2 += v * a2s[ff];
        }
        s1 *= LOG2E;
        s2 *= LOG2E;
        g_f1[rowbase + t] = s1;
        g_f2[rowbase + t] = s2;
        float m = s2;
        #pragma unroll
        for (int off = 16; off > 0; off >>= 1)
            m = fmaxf(m, __shfl_xor_sync(0xffffffffu, m, off));
        if (t == 0) atomicMax(&g_m2i, enc_f(m));
    }
}

// ---------------------------------------------------------------------------
// Kernel 2: R9 skeleton + fm SMEM table (ONLY change vs proven 82.4 config).
// Warp owns 16 M-rows. adj: per-row LDG.64 (lane l -> cols 2l,2l+1).
// Gen: per-row (f1, mrow) via broadcast LDS.64 (replaces 32-shfl chain).
// B: packed fragments via coalesced LDG.64 (L1-resident, shared by 16 warps).
// Grid (64, 4), 256 threads, 2 CTAs/SM. No __syncthreads in main loop.
// ---------------------------------------------------------------------------
#define ROWB 144                       // A row stride bytes (72 halves)
#define AW_BYTES (16 * ROWB)           // 2304 per warp
#define SM_F2 (8 * AW_BYTES)           // 18432
#define SM_FM (SM_F2 + (NN / JSPLIT) * 4)      // 26624 (128 rows x float2)
#define DYN_SMEM (SM_FM + 128 * 8)             // 27648

__global__ void __launch_bounds__(256, 2)
k_attn(const int* __restrict__ adj) {
    extern __shared__ __align__(16) char smraw[];
    float* f2s = (float*)(smraw + SM_F2);
    uint32_t smbase = smem_u32(smraw);

    int t   = threadIdx.x;
    int w   = t >> 5;
    int l   = t & 31;
    int ib  = blockIdx.x * TI;
    int split = blockIdx.y;
    int jb0 = split * (NN / JSPLIT);

    // stage f2 slice (2048 floats) + per-row (f1, mrow) table
    #pragma unroll
    for (int q = 0; q < 2; q++) {
        int idx = t + q * 256;
        ((float4*)f2s)[idx] = ((const float4*)(g_f2 + jb0))[idx];
    }
    float M2 = dec_f(g_m2i);
    if (t < 128) {
        float f1v = g_f1[ib + t];
        float mt = f1v + M2;
        *(float2*)(smraw + SM_FM + t * 8) =
            make_float2(f1v, fmaxf(mt, LALPHA * mt));
    }
    __syncthreads();

    // adj: lane l covers cols 2l,2l+1; row rr at +rr*NN
    const char* adjbase =
        (const char*)(adj + (size_t)(ib + w * 16) * NN + jb0 + l * 2);

    char* aw = smraw + w * AW_BYTES;                  // warp A buffer
    uint32_t aw_u32 = smbase + w * AW_BYTES;
    const char* fmbase = smraw + SM_FM + (w * 16) * 8;

    // mma fragment statics
    int lq = l >> 2;
    int lr = l & 3;
    int m_id = l >> 3, lr8 = l & 7;
    uint32_t a_off = (uint32_t)((lr8 + (m_id & 1) * 8) * ROWB + (m_id >> 1) * 16);
    // B: packed fragments; per tile base index = Tg*1024 + l
    const uint2* bbase = g_Bpk + (size_t)(split * NTILES) * 1024 + l;
    uint32_t onesb = (lq == 0) ? 0x3C003C00u : 0u;    // denominator frag

    float acc[9][4];
    #pragma unroll
    for (int i = 0; i < 9; i++)
        #pragma unroll
        for (int j = 0; j < 4; j++) acc[i][j] = 0.f;

    // prefetch adj tile 0 (16 rows, coalesced LDG.64)
    int2 av[16];
    #pragma unroll
    for (int rr = 0; rr < 16; rr++)
        av[rr] = *(const int2*)(adjbase + (size_t)rr * (NN * 4));

    for (int tile = 0; tile < NTILES; tile++) {
        // ---- gen: 16 rows, lane handles 2 cols; fm via broadcast LDS.64 ----
        float2 f2p = *(const float2*)(f2s + tile * TJ + 2 * l);
        #pragma unroll
        for (int rr = 0; rr < 16; rr++) {
            float2 fm = *(const float2*)(fmbase + rr * 8);
            int2 am = av[rr];
            float e0 = fm.x + f2p.x;
            float e1 = fm.x + f2p.y;
            e0 = fmaxf(e0, LALPHA * e0) - fm.y;
            e1 = fmaxf(e1, LALPHA * e1) - fm.y;
            float p0 = (am.x > 0) ? ex2(e0) : 0.f;
            float p1 = (am.y > 0) ? ex2(e1) : 0.f;
            *(uint32_t*)(aw + rr * ROWB + l * 4) =
                h2_u32(__floats2half2_rn(p0, p1));
        }
        // prefetch next adj tile (flies across the MMA phase)
        if (tile + 1 < NTILES) {
            const char* nb_ = adjbase + (size_t)(tile + 1) * (TJ * 4);
            #pragma unroll
            for (int rr = 0; rr < 16; rr++)
                av[rr] = *(const int2*)(nb_ + (size_t)rr * (NN * 4));
        }
        __syncwarp();

        // ---- MMA: A from warp SMEM, B from packed global (coalesced) ----
        const uint2* bt = bbase + (size_t)tile * 1024;
        #pragma unroll
        for (int kk = 0; kk < 4; kk++) {
            uint32_t a0, a1, a2, a3;
            ldsm_x4(a0, a1, a2, a3, aw_u32 + a_off + kk * 32);
            #pragma unroll
            for (int nb = 0; nb < 8; nb++) {
                uint2 b = bt[kk * 256 + nb * 32];
                mma_f16(acc[nb], a0, a1, a2, a3, b.x, b.y);
            }
            mma_f16(acc[8], a0, a1, a2, a3, onesb, onesb);
        }
        __syncwarp();   // A buffer reuse: all lanes' LDSM done before next gen
    }

    // epilogue: numerator partials + denominator (acc[8])
    int r0 = w * 16;
    #pragma unroll
    for (int nb = 0; nb < 8; nb++) {
        int row0 = ib + r0 + lq;
        int col  = nb * 8 + 2 * lr;
        *(float2*)(g_acc[split] + (size_t)row0 * OUT_F + col) =
            make_float2(acc[nb][0], acc[nb][1]);
        *(float2*)(g_acc[split] + (size_t)(row0 + 8) * OUT_F + col) =
            make_float2(acc[nb][2], acc[nb][3]);
    }
    if (lr == 0) {
        g_s[split][ib + r0 + lq]     = acc[8][0];
        g_s[split][ib + r0 + 8 + lq] = acc[8][2];
    }
}

// ---------------------------------------------------------------------------
// Kernel 3 (R13, proven): combine splits, normalize, ELU — float4/thread.
// ---------------------------------------------------------------------------
__global__ void k_final(float* __restrict__ out) {
    int q = blockIdx.x * 512 + threadIdx.x;   // float4 index (16 per row)
    int row = q >> 4;
    float s = 0.f;
    float4 v = make_float4(0.f, 0.f, 0.f, 0.f);
    #pragma unroll
    for (int sp = 0; sp < JSPLIT; sp++) {
        s += g_s[sp][row];
        float4 p = ((const float4*)g_acc[sp])[q];
        v.x += p.x; v.y += p.y; v.z += p.z; v.w += p.w;
    }
    float inv = 1.f / s;
    float r0 = v.x * inv, r1 = v.y * inv, r2 = v.z * inv, r3 = v.w * inv;
    float4 o;
    o.x = r0 > 0.f ? r0 : (__expf(r0) - 1.f);
    o.y = r1 > 0.f ? r1 : (__expf(r1) - 1.f);
    o.z = r2 > 0.f ? r2 : (__expf(r2) - 1.f);
    o.w = r3 > 0.f ? r3 : (__expf(r3) - 1.f);
    ((float4*)out)[q] = o;
}

// ---------------------------------------------------------------------------
extern "C" void kernel_launch(void* const* d_in, const int* in_sizes, int n_in,
                              void* d_out, int out_size) {
    const float* h   = (const float*)d_in[0];
    const int*   adj = (const int*)d_in[1];
    const float* W   = (const float*)d_in[2];
    const float* a   = (const float*)d_in[3];
    float* out = (float*)d_out;

    cudaFuncSetAttribute(k_prep, cudaFuncAttributeMaxDynamicSharedMemorySize,
                         P_SMEM);
    cudaFuncSetAttribute(k_attn, cudaFuncAttributeMaxDynamicSharedMemorySize,
                         DYN_SMEM);

    k_prep<<<NN / 32, 512, P_SMEM>>>(h, W, a);
    dim3 g2(NN / TI, JSPLIT);
    k_attn<<<g2, 256, DYN_SMEM>>>(adj);
    k_final<<<(NN * OUT_F) / (4 * 512), 512>>>(out);
}

// round 15
// speedup vs baseline: 1.1000x; 1.1000x over previous
#include <cuda_runtime.h>
#include <cuda_fp16.h>
#include <cstdint>

#define NN 8192
#define IN_F 128
#define OUT_F 64
#define TI 128
#define TJ 64
#define JSPLIT 4
#define LALPHA 0.2f
#define NTILES ((NN / JSPLIT) / TJ)   // 32
#define LOG2E 1.4426950408889634f

// -------- scratch (allocation-free) --------
// B in mma-fragment order: [tile 128][kk 4][nb 8][lane 32] x uint2
__device__ uint2 g_Bpk[128 * 4 * 8 * 32];
__device__ float g_f1[NN];                   // pre-scaled by log2(e)
__device__ float g_f2[NN];                   // pre-scaled by log2(e)
__device__ float g_acc[JSPLIT][NN * OUT_F];
__device__ float g_s[JSPLIT][NN];
__device__ int   g_m2i = 0x80000000;         // encoded max(f2_scaled)

__device__ __forceinline__ int enc_f(float x) {
    int k = __float_as_int(x);
    return (k < 0) ? (k ^ 0x7FFFFFFF) : k;
}
__device__ __forceinline__ float dec_f(int k) {
    return __int_as_float((k < 0) ? (k ^ 0x7FFFFFFF) : k);
}
__device__ __forceinline__ uint32_t h2_u32(__half2 h) {
    uint32_t u;
    *(__half2*)&u = h;
    return u;
}
__device__ __forceinline__ float ex2(float x) {
    float y;
    asm("ex2.approx.ftz.f32 %0, %1;" : "=f"(y) : "f"(x));
    return y;
}
__device__ __forceinline__ uint32_t smem_u32(const void* p) {
    uint32_t a;
    asm("{ .reg .u64 t; cvta.to.shared.u64 t, %1; cvt.u32.u64 %0, t; }"
        : "=r"(a) : "l"(p));
    return a;
}
__device__ __forceinline__ void ldsm_x4(uint32_t& r0, uint32_t& r1,
                                        uint32_t& r2, uint32_t& r3,
                                        uint32_t addr) {
    asm volatile("ldmatrix.sync.aligned.m8n8.x4.shared.b16 {%0,%1,%2,%3}, [%4];"
                 : "=r"(r0), "=r"(r1), "=r"(r2), "=r"(r3) : "r"(addr));
}

// m16n8k16 fp16 mma, fp32 accum
__device__ __forceinline__ void mma_f16(float* c, uint32_t a0, uint32_t a1,
                                        uint32_t a2, uint32_t a3,
                                        uint32_t b0, uint32_t b1) {
    asm volatile(
        "mma.sync.aligned.m16n8k16.row.col.f32.f16.f16.f32 "
        "{%0,%1,%2,%3}, {%4,%5,%6,%7}, {%8,%9}, {%0,%1,%2,%3};"
        : "+f"(c[0]), "+f"(c[1]), "+f"(c[2]), "+f"(c[3])
        : "r"(a0), "r"(a1), "r"(a2), "r"(a3), "r"(b0), "r"(b1));
}

// ---------------------------------------------------------------------------
// Kernel 1: Wh = h @ W ; packed B fragments ; f1, f2 (log2e-scaled)
// R12 skeleton (32 rows/block x 512 thr, one wave) with VECTORIZED h reads:
// per k4: 4x LDS.32 (W, broadcast) + 4x LDS.128 (h rows) for 16 FFMA
// (was 20x LDS.32). W layout and FFMA order unchanged -> bit-identical.
// ---------------------------------------------------------------------------
#define P_SMEM (14496 * 4)   // Ws 8192 | hs 4096 | whs 2080 | a1s 64 | a2s 64

__global__ void __launch_bounds__(512, 2)
k_prep(const float* __restrict__ h,
       const float* __restrict__ W,
       const float* __restrict__ a) {
    extern __shared__ __align__(16) float psm[];
    float* Ws = psm;                                   // [128*64]
    float (*hs)[IN_F] = (float (*)[IN_F])(psm + 8192); // [32][128]
    float (*whs)[65]  = (float (*)[65])(psm + 12288);  // [32][65]
    float* a1s = psm + 14368;
    float* a2s = psm + 14432;

    int t = threadIdx.x;
    int rowbase = blockIdx.x * 32;

    #pragma unroll
    for (int q = 0; q < 4; q++)
        ((float4*)Ws)[t + q * 512] = ((const float4*)W)[t + q * 512];
    #pragma unroll
    for (int q = 0; q < 2; q++)
        ((float4*)hs)[t + q * 512] =
            ((const float4*)(h + (size_t)rowbase * IN_F))[t + q * 512];
    if (t < OUT_F) { a1s[t] = a[t]; a2s[t] = a[OUT_F + t]; }
    __syncthreads();

    int f  = t & 63;
    int rg = t >> 6;          // 0..7, 4 rows each
    float acc[4] = {0.f, 0.f, 0.f, 0.f};
    const float4* h0 = (const float4*)&hs[rg * 4 + 0][0];
    const float4* h1 = (const float4*)&hs[rg * 4 + 1][0];
    const float4* h2 = (const float4*)&hs[rg * 4 + 2][0];
    const float4* h3 = (const float4*)&hs[rg * 4 + 3][0];
    #pragma unroll 4
    for (int k4 = 0; k4 < IN_F / 4; k4++) {
        float w0 = Ws[(k4 * 4 + 0) * OUT_F + f];
        float w1 = Ws[(k4 * 4 + 1) * OUT_F + f];
        float w2 = Ws[(k4 * 4 + 2) * OUT_F + f];
        float w3 = Ws[(k4 * 4 + 3) * OUT_F + f];
        float4 v0 = h0[k4], v1 = h1[k4], v2 = h2[k4], v3 = h3[k4];
        acc[0] += v0.x * w0 + v0.y * w1 + v0.z * w2 + v0.w * w3;
        acc[1] += v1.x * w0 + v1.y * w1 + v1.z * w2 + v1.w * w3;
        acc[2] += v2.x * w0 + v2.y * w1 + v2.z * w2 + v2.w * w3;
        acc[3] += v3.x * w0 + v3.y * w1 + v3.z * w2 + v3.w * w3;
    }
    #pragma unroll
    for (int rr = 0; rr < 4; rr++) whs[rg * 4 + rr][f] = acc[rr];
    __syncthreads();

    // packed B fragment store: two 16-row groups per block.
    {
        int grp = t >> 8;            // 0/1
        int tt  = t & 255;
        int nb  = tt >> 5, l = tt & 31;
        int n   = nb * 8 + (l >> 2);
        int jl  = grp * 16 + (l & 3) * 2;
        __half2 w0 = __floats2half2_rn(whs[jl][n],     whs[jl + 1][n]);
        __half2 w1 = __floats2half2_rn(whs[jl + 8][n], whs[jl + 9][n]);
        int rb = rowbase + grp * 16;
        int T  = rb >> 6;
        int kk = (rb >> 4) & 3;
        size_t idx = ((size_t)(T * 4 + kk) * 8 + nb) * 32 + l;
        g_Bpk[idx] = make_uint2(h2_u32(w0), h2_u32(w1));
    }

    if (t < 32) {
        float s1 = 0.f, s2 = 0.f;
        #pragma unroll 8
        for (int ff = 0; ff < OUT_F; ff++) {
            float v = whs[t][ff];
            s1 += v * a1s[ff];
            s2 += v * a2s[ff];
        }
        s1 *= LOG2E;
        s2 *= LOG2E;
        g_f1[rowbase + t] = s1;
        g_f2[rowbase + t] = s2;
        float m = s2;
        #pragma unroll
        for (int off = 16; off > 0; off >>= 1)
            m = fmaxf(m, __shfl_xor_sync(0xffffffffu, m, off));
        if (t == 0) atomicMax(&g_m2i, enc_f(m));
    }
}

// ---------------------------------------------------------------------------
// Kernel 2 (byte-exact R9, proven 82.4us): sync-free warp-decoupled kernel.
// Warp owns 16 M-rows. adj: per-row LDG.64 (lane l -> cols 2l,2l+1).
// Gen: row loop with f1/mrow shfl-broadcast -> warp-private A SMEM.
// B: packed fragments via coalesced LDG.64 (L1-resident, shared by 16 warps).
// Grid (64, 4), 256 threads, 2 CTAs/SM. No __syncthreads in main loop.
// ---------------------------------------------------------------------------
#define ROWB 144                       // A row stride bytes (72 halves)
#define AW_BYTES (16 * ROWB)           // 2304 per warp
#define SM_F2 (8 * AW_BYTES)           // 18432
#define DYN_SMEM (SM_F2 + (NN / JSPLIT) * 4)   // 26624

__global__ void __launch_bounds__(256, 2)
k_attn(const int* __restrict__ adj) {
    extern __shared__ __align__(16) char smraw[];
    float* f2s = (float*)(smraw + SM_F2);
    uint32_t smbase = smem_u32(smraw);

    int t   = threadIdx.x;
    int w   = t >> 5;
    int l   = t & 31;
    int ib  = blockIdx.x * TI;
    int split = blockIdx.y;
    int jb0 = split * (NN / JSPLIT);

    // stage f2 slice (2048 floats) — only block-wide sync in the kernel
    #pragma unroll
    for (int q = 0; q < 2; q++) {
        int idx = t + q * 256;
        ((float4*)f2s)[idx] = ((const float4*)(g_f2 + jb0))[idx];
    }
    __syncthreads();

    // per-lane row constants (lanes 0..15 meaningful, others mirror)
    float M2 = dec_f(g_m2i);
    float f1r_l = g_f1[ib + w * 16 + (l & 15)];
    float mt = f1r_l + M2;
    float mrow_l = fmaxf(mt, LALPHA * mt);

    // adj: lane l covers cols 2l,2l+1; row rr at +rr*NN
    const char* adjbase =
        (const char*)(adj + (size_t)(ib + w * 16) * NN + jb0 + l * 2);

    char* aw = smraw + w * AW_BYTES;                  // warp A buffer
    uint32_t aw_u32 = smbase + w * AW_BYTES;

    // mma fragment statics
    int lq = l >> 2;
    int lr = l & 3;
    int m_id = l >> 3, lr8 = l & 7;
    uint32_t a_off = (uint32_t)((lr8 + (m_id & 1) * 8) * ROWB + (m_id >> 1) * 16);
    // B: packed fragments; per tile base index = Tg*1024 + l
    const uint2* bbase = g_Bpk + (size_t)(split * NTILES) * 1024 + l;
    uint32_t onesb = (lq == 0) ? 0x3C003C00u : 0u;    // denominator frag

    float acc[9][4];
    #pragma unroll
    for (int i = 0; i < 9; i++)
        #pragma unroll
        for (int j = 0; j < 4; j++) acc[i][j] = 0.f;

    // prefetch adj tile 0 (16 rows, coalesced LDG.64)
    int2 av[16];
    #pragma unroll
    for (int rr = 0; rr < 16; rr++)
        av[rr] = *(const int2*)(adjbase + (size_t)rr * (NN * 4));

    for (int tile = 0; tile < NTILES; tile++) {
        // ---- gen: 16 rows, lane handles 2 cols ----
        float2 f2p = *(const float2*)(f2s + tile * TJ + 2 * l);
        #pragma unroll
        for (int rr = 0; rr < 16; rr++) {
            float f1b = __shfl_sync(0xffffffffu, f1r_l, rr);
            float mb  = __shfl_sync(0xffffffffu, mrow_l, rr);
            int2 am = av[rr];
            float e0 = f1b + f2p.x;
            float e1 = f1b + f2p.y;
            e0 = fmaxf(e0, LALPHA * e0) - mb;
            e1 = fmaxf(e1, LALPHA * e1) - mb;
            float p0 = (am.x > 0) ? ex2(e0) : 0.f;
            float p1 = (am.y > 0) ? ex2(e1) : 0.f;
            *(uint32_t*)(aw + rr * ROWB + l * 4) =
                h2_u32(__floats2half2_rn(p0, p1));
        }
        // prefetch next adj tile (flies across the MMA phase)
        if (tile + 1 < NTILES) {
            const char* nb_ = adjbase + (size_t)(tile + 1) * (TJ * 4);
            #pragma unroll
            for (int rr = 0; rr < 16; rr++)
                av[rr] = *(const int2*)(nb_ + (size_t)rr * (NN * 4));
        }
        __syncwarp();

        // ---- MMA: A from warp SMEM, B from packed global (coalesced) ----
        const uint2* bt = bbase + (size_t)tile * 1024;
        #pragma unroll
        for (int kk = 0; kk < 4; kk++) {
            uint32_t a0, a1, a2, a3;
            ldsm_x4(a0, a1, a2, a3, aw_u32 + a_off + kk * 32);
            #pragma unroll
            for (int nb = 0; nb < 8; nb++) {
                uint2 b = bt[kk * 256 + nb * 32];
                mma_f16(acc[nb], a0, a1, a2, a3, b.x, b.y);
            }
            mma_f16(acc[8], a0, a1, a2, a3, onesb, onesb);
        }
        __syncwarp();   // A buffer reuse: all lanes' LDSM done before next gen
    }

    // epilogue: numerator partials + denominator (acc[8])
    int r0 = w * 16;
    #pragma unroll
    for (int nb = 0; nb < 8; nb++) {
        int row0 = ib + r0 + lq;
        int col  = nb * 8 + 2 * lr;
        *(float2*)(g_acc[split] + (size_t)row0 * OUT_F + col) =
            make_float2(acc[nb][0], acc[nb][1]);
        *(float2*)(g_acc[split] + (size_t)(row0 + 8) * OUT_F + col) =
            make_float2(acc[nb][2], acc[nb][3]);
    }
    if (lr == 0) {
        g_s[split][ib + r0 + lq]     = acc[8][0];
        g_s[split][ib + r0 + 8 + lq] = acc[8][2];
    }
}

// ---------------------------------------------------------------------------
// Kernel 3 (R13, proven): combine splits, normalize, ELU — float4/thread.
// ---------------------------------------------------------------------------
__global__ void k_final(float* __restrict__ out) {
    int q = blockIdx.x * 512 + threadIdx.x;   // float4 index (16 per row)
    int row = q >> 4;
    float s = 0.f;
    float4 v = make_float4(0.f, 0.f, 0.f, 0.f);
    #pragma unroll
    for (int sp = 0; sp < JSPLIT; sp++) {
        s += g_s[sp][row];
        float4 p = ((const float4*)g_acc[sp])[q];
        v.x += p.x; v.y += p.y; v.z += p.z; v.w += p.w;
    }
    float inv = 1.f / s;
    float r0 = v.x * inv, r1 = v.y * inv, r2 = v.z * inv, r3 = v.w * inv;
    float4 o;
    o.x = r0 > 0.f ? r0 : (__expf(r0) - 1.f);
    o.y = r1 > 0.f ? r1 : (__expf(r1) - 1.f);
    o.z = r2 > 0.f ? r2 : (__expf(r2) - 1.f);
    o.w = r3 > 0.f ? r3 : (__expf(r3) - 1.f);
    ((float4*)out)[q] = o;
}

// ---------------------------------------------------------------------------
extern "C" void kernel_launch(void* const* d_in, const int* in_sizes, int n_in,
                              void* d_out, int out_size) {
    const float* h   = (const float*)d_in[0];
    const int*   adj = (const int*)d_in[1];
    const float* W   = (const float*)d_in[2];
    const float* a   = (const float*)d_in[3];
    float* out = (float*)d_out;

    cudaFuncSetAttribute(k_prep, cudaFuncAttributeMaxDynamicSharedMemorySize,
                         P_SMEM);
    cudaFuncSetAttribute(k_attn, cudaFuncAttributeMaxDynamicSharedMemorySize,
                         DYN_SMEM);

    k_prep<<<NN / 32, 512, P_SMEM>>>(h, W, a);
    dim3 g2(NN / TI, JSPLIT);
    k_attn<<<g2, 256, DYN_SMEM>>>(adj);
    k_final<<<(NN * OUT_F) / (4 * 512), 512>>>(out);
}